// round 1
// baseline (speedup 1.0000x reference)
#include <cuda_runtime.h>
#include <cstdint>
#include <math.h>

// ---------------- problem constants ----------------
namespace cfg {
constexpr int Bb    = 2;
constexpr int Ss    = 4096;
constexpr int DM    = 3584;
constexpr int Hh    = 112;
constexpr int DH    = 64;
constexpr int CHUNK = 256;
constexpr int INNER = Hh * DH;          // 7168
constexpr int M1    = Bb * Ss;          // 8192 rows (tokens)
constexpr int N1    = 2 * INNER;        // 14336 (x|z)
constexpr int K1    = DM;               // 3584
constexpr int N2    = DM;               // 3584
constexpr int K2    = INNER;            // 7168
constexpr int NCH   = Ss / CHUNK;       // 16 chunks
}

// ---------------- scratch (no cudaMalloc allowed) ----------------
__device__ float g_xz[(size_t)cfg::M1 * cfg::N1];   // ~470 MB
__device__ float g_y [(size_t)cfg::M1 * cfg::K2];   // ~235 MB

// ---------------- tf32 helpers ----------------
__device__ __forceinline__ uint32_t f2tf32(float x) {
    uint32_t u;
    asm("cvt.rna.tf32.f32 %0, %1;" : "=r"(u) : "f"(x));
    return u;
}

__device__ __forceinline__ void mma_m16n8k8(float d[4], const uint32_t a[4], const uint32_t b[2]) {
    asm volatile(
        "mma.sync.aligned.m16n8k8.row.col.f32.tf32.tf32.f32 "
        "{%0,%1,%2,%3}, {%4,%5,%6,%7}, {%8,%9}, {%0,%1,%2,%3};"
        : "+f"(d[0]), "+f"(d[1]), "+f"(d[2]), "+f"(d[3])
        : "r"(a[0]), "r"(a[1]), "r"(a[2]), "r"(a[3]),
          "r"(b[0]), "r"(b[1]));
}

// ---------------- GEMM: C[M,N] = A[M,K] * B[N,K]^T  (all row-major fp32, tf32 mma) ----------------
// BM=128, BN=128, BK=16, 256 threads, 8 warps as 2x4 (warp tile 64x32)
#define BM 128
#define BN 128
#define BKT 16
#define SST 20  // padded smem k-stride (conflict-free fragment loads)

__global__ __launch_bounds__(256)
void gemm_tf32_nt(const float* __restrict__ A, const float* __restrict__ Bm,
                  float* __restrict__ C, int M, int N, int K)
{
    __shared__ uint32_t As[2][BM * SST];
    __shared__ uint32_t Bs[2][BN * SST];

    // ---- L2-friendly tile swizzle (grouped rows) ----
    const int nTn = N / BN, nTm = M / BM;
    const int pid = blockIdx.x;
    constexpr int GROUP = 8;
    const int npg     = GROUP * nTn;
    const int gidx    = pid / npg;
    const int first_m = gidx * GROUP;
    const int gsz     = min(nTm - first_m, GROUP);
    const int inG     = pid % npg;
    const int tm      = first_m + (inG % gsz);
    const int tn      = inG / gsz;

    const int tid  = threadIdx.x;
    const int lane = tid & 31;
    const int wid  = tid >> 5;
    const int gq   = lane >> 2;     // group id (0..7)
    const int tg   = lane & 3;      // thread-in-group (0..3)
    const int m_w  = (wid >> 2) * 64;  // warp row base within tile
    const int n_w  = (wid & 3) * 32;   // warp col base within tile

    // ---- global load mapping: each thread loads 2 float4 per operand per k-tile ----
    const int lrow = tid >> 2;          // 0..63
    const int lk   = (tid & 3) << 2;    // 0,4,8,12
    const float* Ag = A  + (size_t)(tm * BM + lrow) * K + lk;
    const float* Bg = Bm + (size_t)(tn * BN + lrow) * K + lk;
    const size_t rstep = (size_t)64 * K;

    float4 pa0, pa1, pb0, pb1;
    pa0 = *(const float4*)(Ag);
    pa1 = *(const float4*)(Ag + rstep);
    pb0 = *(const float4*)(Bg);
    pb1 = *(const float4*)(Bg + rstep);

    auto stash = [&](int buf) {
        uint4 u;
        u.x = f2tf32(pa0.x); u.y = f2tf32(pa0.y); u.z = f2tf32(pa0.z); u.w = f2tf32(pa0.w);
        *(uint4*)&As[buf][lrow * SST + lk] = u;
        u.x = f2tf32(pa1.x); u.y = f2tf32(pa1.y); u.z = f2tf32(pa1.z); u.w = f2tf32(pa1.w);
        *(uint4*)&As[buf][(lrow + 64) * SST + lk] = u;
        u.x = f2tf32(pb0.x); u.y = f2tf32(pb0.y); u.z = f2tf32(pb0.z); u.w = f2tf32(pb0.w);
        *(uint4*)&Bs[buf][lrow * SST + lk] = u;
        u.x = f2tf32(pb1.x); u.y = f2tf32(pb1.y); u.z = f2tf32(pb1.z); u.w = f2tf32(pb1.w);
        *(uint4*)&Bs[buf][(lrow + 64) * SST + lk] = u;
    };

    stash(0);
    __syncthreads();

    float acc[4][4][4];
    #pragma unroll
    for (int i = 0; i < 4; i++)
        #pragma unroll
        for (int j = 0; j < 4; j++)
            #pragma unroll
            for (int r = 0; r < 4; r++) acc[i][j][r] = 0.f;

    const int nk = K / BKT;
    for (int kt = 0; kt < nk; ++kt) {
        const int cur = kt & 1;
        if (kt + 1 < nk) {
            const float* A2 = Ag + (size_t)(kt + 1) * BKT;
            const float* B2 = Bg + (size_t)(kt + 1) * BKT;
            pa0 = *(const float4*)(A2);
            pa1 = *(const float4*)(A2 + rstep);
            pb0 = *(const float4*)(B2);
            pb1 = *(const float4*)(B2 + rstep);
        }

        #pragma unroll
        for (int k8 = 0; k8 < 2; ++k8) {
            uint32_t af[4][4];
            uint32_t bf[4][2];
            #pragma unroll
            for (int mt = 0; mt < 4; mt++) {
                const int m0 = m_w + mt * 16 + gq;
                const uint32_t* p = &As[cur][m0 * SST + k8 * 8 + tg];
                af[mt][0] = p[0];
                af[mt][1] = p[8 * SST];
                af[mt][2] = p[4];
                af[mt][3] = p[8 * SST + 4];
            }
            #pragma unroll
            for (int nt = 0; nt < 4; nt++) {
                const int n0 = n_w + nt * 8 + gq;
                const uint32_t* p = &Bs[cur][n0 * SST + k8 * 8 + tg];
                bf[nt][0] = p[0];
                bf[nt][1] = p[4];
            }
            #pragma unroll
            for (int mt = 0; mt < 4; mt++)
                #pragma unroll
                for (int nt = 0; nt < 4; nt++)
                    mma_m16n8k8(acc[mt][nt], af[mt], bf[nt]);
        }

        if (kt + 1 < nk) stash(cur ^ 1);
        __syncthreads();
    }

    // ---- epilogue: c0,c1 at (row gq, cols 2tg,2tg+1); c2,c3 at row gq+8 ----
    #pragma unroll
    for (int mt = 0; mt < 4; mt++) {
        const int r0 = tm * BM + m_w + mt * 16 + gq;
        #pragma unroll
        for (int nt = 0; nt < 4; nt++) {
            const int c0 = tn * BN + n_w + nt * 8 + tg * 2;
            float2* p0 = (float2*)&C[(size_t)r0 * N + c0];
            float2* p1 = (float2*)&C[(size_t)(r0 + 8) * N + c0];
            *p0 = make_float2(acc[mt][nt][0], acc[mt][nt][1]);
            *p1 = make_float2(acc[mt][nt][2], acc[mt][nt][3]);
        }
    }
}

// ---------------- scan + sigmoid gate ----------------
// For each (b, t, h, d): h_c = h_{c-1}*A[h] + 0.1*x[b, c*CHUNK+t, h, d]; y = h_c * sigmoid(z)
__global__ __launch_bounds__(256)
void scan_gate_kernel(const float* __restrict__ A_log,
                      const float* __restrict__ xz,
                      float* __restrict__ y)
{
    using namespace cfg;
    const int idx   = blockIdx.x * blockDim.x + threadIdx.x;  // over Bb*CHUNK*INNER
    const int inner = idx % INNER;
    const int bt    = idx / INNER;
    const int t     = bt % CHUNK;
    const int b     = bt / CHUNK;

    const float Ah = expf(-fabsf(A_log[inner >> 6]));  // head = inner/64
    float hstate = 0.f;

    size_t xrow = ((size_t)b * Ss + t) * (size_t)N1 + inner;
    size_t yrow = ((size_t)b * Ss + t) * (size_t)INNER + inner;
    const size_t xstep = (size_t)CHUNK * N1;
    const size_t ystep = (size_t)CHUNK * INNER;

    #pragma unroll
    for (int c = 0; c < NCH; c++) {
        const float xv = xz[xrow];
        const float zv = xz[xrow + INNER];
        hstate = hstate * Ah + 0.1f * xv;
        const float sig = 1.f / (1.f + expf(-zv));
        y[yrow] = hstate * sig;
        xrow += xstep;
        yrow += ystep;
    }
}

// ---------------- launch ----------------
extern "C" void kernel_launch(void* const* d_in, const int* in_sizes, int n_in,
                              void* d_out, int out_size)
{
    using namespace cfg;
    const float* hs    = (const float*)d_in[0];  // [B,S,DM]
    const float* W_in  = (const float*)d_in[1];  // [2*INNER, DM]
    const float* W_out = (const float*)d_in[2];  // [DM, INNER]
    const float* A_log = (const float*)d_in[3];  // [H]
    float* out = (float*)d_out;                  // [B,S,DM]

    float *xz, *y;
    cudaGetSymbolAddress((void**)&xz, g_xz);
    cudaGetSymbolAddress((void**)&y,  g_y);

    // GEMM1: xz = hs @ W_in^T   (M=8192, N=14336, K=3584)
    gemm_tf32_nt<<<(M1 / BM) * (N1 / BN), 256>>>(hs, W_in, xz, M1, N1, K1);

    // scan + gate: y from xz
    const int total = Bb * CHUNK * INNER;     // 3,670,016
    scan_gate_kernel<<<total / 256, 256>>>(A_log, xz, y);

    // GEMM2: out = y @ W_out^T  (M=8192, N=3584, K=7168)
    gemm_tf32_nt<<<(M1 / BM) * (N2 / BN), 256>>>(y, W_out, out, M1, N2, K2);
}